// round 2
// baseline (speedup 1.0000x reference)
#include <cuda_runtime.h>

// ============================================================================
// TTLinear: out[B,4096] = x[B,4096] @ W^T + bias, where W is reconstructed
// from the 4 TT-cores.  W[(j0j1j2j3),(i0i1i2i3)] =
//   sum_{a1,a2,a3} core0[j0, i0*16+a1] core1[a1*8+j1, i1*16+a2]
//                  core2[a2*8+j2, i2*16+a3] core3[a3*8+j3, i3]
// ============================================================================

// Scratch (allocation-free rule: __device__ globals)
__device__ float g_M1[16 * 64 * 64];            // [a2][j2j3][i2i3]      256 KB
__device__ float g_M2[16 * 8 * 64 * 8 * 64];    // [a1][j1][j23][i1][i23] 16 MB
__device__ float g_W[4096u * 4096u];            // [j][i] row-major       64 MB

// ---------------------------------------------------------------------------
// Step 1: M1[a2, j2 j3, i2 i3] = sum_a3 core2[a2*8+j2, i2*16+a3] * core3[a3*8+j3, i3]
__global__ void compose_m1(const float* __restrict__ core2,
                           const float* __restrict__ core3) {
    int t = blockIdx.x * blockDim.x + threadIdx.x;   // 65536
    int i23 = t & 63, i2 = i23 >> 3, i3 = i23 & 7;
    int j23 = (t >> 6) & 63, j2 = j23 >> 3, j3 = j23 & 7;
    int a2 = t >> 12;
    float s = 0.f;
#pragma unroll
    for (int a3 = 0; a3 < 16; ++a3)
        s += core2[(a2 * 8 + j2) * 128 + i2 * 16 + a3] *
             core3[(a3 * 8 + j3) * 8 + i3];
    g_M1[t] = s;   // t == (a2*64 + j23)*64 + i23
}

// ---------------------------------------------------------------------------
// Step 2: M2[a1, j1, j23, i1, i23] = sum_a2 core1[a1*8+j1, i1*16+a2] * M1[a2, j23, i23]
__global__ void compose_m2(const float* __restrict__ core1) {
    int t = blockIdx.x * blockDim.x + threadIdx.x;   // 4194304
    int i23 = t & 63;
    int i1  = (t >> 6) & 7;
    int j23 = (t >> 9) & 63;
    int j1  = (t >> 15) & 7;
    int a1  = t >> 18;
    float s = 0.f;
#pragma unroll
    for (int a2 = 0; a2 < 16; ++a2)
        s += core1[(a1 * 8 + j1) * 128 + i1 * 16 + a2] *
             g_M1[(a2 * 64 + j23) * 64 + i23];
    g_M2[t] = s;
}

// ---------------------------------------------------------------------------
// Step 3: W[(j0*512+j123), (i0*512+i123)] = sum_a1 core0[j0, i0*16+a1] * M2[a1,...]
// One thread per (j123, i123); 64 outputs per thread, M2 read exactly once.
__global__ void compose_w(const float* __restrict__ core0) {
    __shared__ float s_c0[1024];
    for (int i = threadIdx.x; i < 1024; i += blockDim.x) s_c0[i] = core0[i];
    __syncthreads();

    int t = blockIdx.x * blockDim.x + threadIdx.x;   // 262144
    int i123 = t & 511, i1 = i123 >> 6, i23 = i123 & 63;
    int j123 = t >> 9,  j1 = j123 >> 6, j23 = j123 & 63;

    float m2v[16];
#pragma unroll
    for (int a1 = 0; a1 < 16; ++a1)
        m2v[a1] = g_M2[(((a1 * 8 + j1) * 64 + j23) * 8 + i1) * 64 + i23];

#pragma unroll
    for (int j0 = 0; j0 < 8; ++j0) {
#pragma unroll
        for (int i0 = 0; i0 < 8; ++i0) {
            float s = 0.f;
#pragma unroll
            for (int a1 = 0; a1 < 16; ++a1)
                s += s_c0[j0 * 128 + i0 * 16 + a1] * m2v[a1];
            g_W[(size_t)(j0 * 512 + j123) * 4096 + (size_t)(i0 * 512 + i123)] = s;
        }
    }
}

// ---------------------------------------------------------------------------
// GEMM: C[2048,4096] = A[2048,4096] @ W[4096,4096]^T + bias
// 128x128x8 tiles, 256 threads, 8x8 per thread, packed f32x2 FMAs.
// ---------------------------------------------------------------------------

#define FMA2(d, a, b) \
    asm("fma.rn.f32x2 %0, %1, %2, %0;" : "+l"(d) : "l"(a), "l"(b))
#define PACK2(d, lo, hi) \
    asm("mov.b64 %0, {%1, %2};" : "=l"(d) : "f"(lo), "f"(hi))
#define UNPACK2(lo, hi, v) \
    asm("mov.b64 {%0, %1}, %2;" : "=f"(lo), "=f"(hi) : "l"(v))

__global__ __launch_bounds__(256, 2)
void tt_gemm(const float* __restrict__ A,
             const float* __restrict__ bias,
             float* __restrict__ C) {
    __shared__ float As[2][8][132];
    __shared__ float Bs[2][8][132];

    const int tid = threadIdx.x;
    const int tx = tid & 15;     // n direction
    const int ty = tid >> 4;     // m direction
    const int bn = blockIdx.x * 128;
    const int bm = blockIdx.y * 128;

    const int lrow = tid >> 1;          // 0..127
    const int lk4  = (tid & 1) * 4;     // 0 or 4

    const float* Ag = A   + (size_t)(bm + lrow) * 4096 + lk4;
    const float* Bg = g_W + (size_t)(bn + lrow) * 4096 + lk4;

    unsigned long long acc[8][4];
#pragma unroll
    for (int i = 0; i < 8; ++i)
#pragma unroll
        for (int j = 0; j < 4; ++j) acc[i][j] = 0ull;

    float4 ra = *(const float4*)Ag;
    float4 rb = *(const float4*)Bg;

    As[0][lk4 + 0][lrow] = ra.x; As[0][lk4 + 1][lrow] = ra.y;
    As[0][lk4 + 2][lrow] = ra.z; As[0][lk4 + 3][lrow] = ra.w;
    Bs[0][lk4 + 0][lrow] = rb.x; Bs[0][lk4 + 1][lrow] = rb.y;
    Bs[0][lk4 + 2][lrow] = rb.z; Bs[0][lk4 + 3][lrow] = rb.w;
    __syncthreads();

    const int NT = 4096 / 8;   // 512 k-tiles
    for (int kt = 0; kt < NT; ++kt) {
        const int buf = kt & 1;
        if (kt + 1 < NT) {
            ra = *(const float4*)(Ag + (size_t)(kt + 1) * 8);
            rb = *(const float4*)(Bg + (size_t)(kt + 1) * 8);
        }
#pragma unroll
        for (int k = 0; k < 8; ++k) {
            float4 a0 = *(const float4*)&As[buf][k][ty * 8];
            float4 a1 = *(const float4*)&As[buf][k][ty * 8 + 4];
            float4 b0 = *(const float4*)&Bs[buf][k][tx * 8];
            float4 b1 = *(const float4*)&Bs[buf][k][tx * 8 + 4];
            unsigned long long bp[4], ap[8];
            PACK2(bp[0], b0.x, b0.y); PACK2(bp[1], b0.z, b0.w);
            PACK2(bp[2], b1.x, b1.y); PACK2(bp[3], b1.z, b1.w);
            PACK2(ap[0], a0.x, a0.x); PACK2(ap[1], a0.y, a0.y);
            PACK2(ap[2], a0.z, a0.z); PACK2(ap[3], a0.w, a0.w);
            PACK2(ap[4], a1.x, a1.x); PACK2(ap[5], a1.y, a1.y);
            PACK2(ap[6], a1.z, a1.z); PACK2(ap[7], a1.w, a1.w);
#pragma unroll
            for (int i = 0; i < 8; ++i)
#pragma unroll
                for (int j = 0; j < 4; ++j)
                    FMA2(acc[i][j], ap[i], bp[j]);
        }
        if (kt + 1 < NT) {
            const int nb = buf ^ 1;
            As[nb][lk4 + 0][lrow] = ra.x; As[nb][lk4 + 1][lrow] = ra.y;
            As[nb][lk4 + 2][lrow] = ra.z; As[nb][lk4 + 3][lrow] = ra.w;
            Bs[nb][lk4 + 0][lrow] = rb.x; Bs[nb][lk4 + 1][lrow] = rb.y;
            Bs[nb][lk4 + 2][lrow] = rb.z; Bs[nb][lk4 + 3][lrow] = rb.w;
            __syncthreads();
        }
    }

    // Epilogue: + bias, float4 stores
    float bv[8];
#pragma unroll
    for (int j = 0; j < 8; ++j) bv[j] = bias[bn + tx * 8 + j];

#pragma unroll
    for (int i = 0; i < 8; ++i) {
        float o[8];
#pragma unroll
        for (int jp = 0; jp < 4; ++jp) {
            float lo, hi;
            UNPACK2(lo, hi, acc[i][jp]);
            o[jp * 2]     = lo + bv[jp * 2];
            o[jp * 2 + 1] = hi + bv[jp * 2 + 1];
        }
        float4* dst = (float4*)&C[(size_t)(bm + ty * 8 + i) * 4096 + bn + tx * 8];
        dst[0] = make_float4(o[0], o[1], o[2], o[3]);
        dst[1] = make_float4(o[4], o[5], o[6], o[7]);
    }
}

// ---------------------------------------------------------------------------
extern "C" void kernel_launch(void* const* d_in, const int* in_sizes, int n_in,
                              void* d_out, int out_size) {
    const float* x     = (const float*)d_in[0];
    const float* core0 = (const float*)d_in[1];
    const float* core1 = (const float*)d_in[2];
    const float* core2 = (const float*)d_in[3];
    const float* core3 = (const float*)d_in[4];
    const float* bias  = (const float*)d_in[5];
    float* out = (float*)d_out;

    compose_m1<<<256, 256>>>(core2, core3);
    compose_m2<<<16384, 256>>>(core1);
    compose_w<<<1024, 256>>>(core0);
    dim3 grid(4096 / 128, 2048 / 128);
    tt_gemm<<<grid, 256>>>(x, bias, out);
}

// round 6
// speedup vs baseline: 2.1308x; 2.1308x over previous
#include <cuda_runtime.h>
#include <cuda_bf16.h>
#include <cstdint>

// ============================================================================
// TTLinear via dense-W reconstruction + split-precision bf16 HMMA GEMM.
//   W = TT(core0..core3);  out = x @ W^T + bias
//   computed as K=12288 bf16 GEMM: A' = [xhi | xhi | xlo], B' = [Whi | Wlo | Whi]
//   (fp32 accumulate -> error ~(2^-9)^2, well under 1e-3).
// NOTE: harness PTX target is plain sm_103 (no 'a') -> tcgen05 unavailable.
// Tensor path used here: mma.sync m16n8k16 bf16 (sm_80+) + cp.async + ldmatrix.
// ============================================================================

// ---------------- device scratch (allocation-free rule) ---------------------
__device__ float g_M1[16 * 64 * 64];                  // 256 KB
__device__ float g_M2[16 * 8 * 64 * 8 * 64];          // 16 MB
__device__ __nv_bfloat16 g_Ap[(size_t)2048 * 12288];  // 50 MB
__device__ __nv_bfloat16 g_Bp[(size_t)4096 * 12288];  // 100 MB

// ---------------------------------------------------------------------------
// Step 1: M1[a2, j2 j3, i2 i3] = sum_a3 core2[a2*8+j2, i2*16+a3] * core3[a3*8+j3, i3]
__global__ void compose_m1(const float* __restrict__ core2,
                           const float* __restrict__ core3) {
    int t = blockIdx.x * blockDim.x + threadIdx.x;
    int i23 = t & 63, i2 = i23 >> 3, i3 = i23 & 7;
    int j23 = (t >> 6) & 63, j2 = j23 >> 3, j3 = j23 & 7;
    int a2 = t >> 12;
    float s = 0.f;
#pragma unroll
    for (int a3 = 0; a3 < 16; ++a3)
        s += core2[(a2 * 8 + j2) * 128 + i2 * 16 + a3] * core3[(a3 * 8 + j3) * 8 + i3];
    g_M1[t] = s;
}

// Step 2: M2[a1, j1, j23, i1, i23] = sum_a2 core1[a1*8+j1, i1*16+a2] * M1[a2, j23, i23]
__global__ void compose_m2(const float* __restrict__ core1) {
    int t = blockIdx.x * blockDim.x + threadIdx.x;
    int i23 = t & 63;
    int i1 = (t >> 6) & 7;
    int j23 = (t >> 9) & 63;
    int j1 = (t >> 15) & 7;
    int a1 = t >> 18;
    float s = 0.f;
#pragma unroll
    for (int a2 = 0; a2 < 16; ++a2)
        s += core1[(a1 * 8 + j1) * 128 + i1 * 16 + a2] * g_M1[(a2 * 64 + j23) * 64 + i23];
    g_M2[t] = s;
}

// Step 3: W row j, col i; emit bf16 hi/lo into B' = [Whi | Wlo | Whi]
__global__ void compose_w(const float* __restrict__ core0) {
    __shared__ float s_c0[1024];
    for (int i = threadIdx.x; i < 1024; i += blockDim.x) s_c0[i] = core0[i];
    __syncthreads();

    int t = blockIdx.x * blockDim.x + threadIdx.x;  // 262144
    int i123 = t & 511, i1 = i123 >> 6, i23 = i123 & 63;
    int j123 = t >> 9, j1 = j123 >> 6, j23 = j123 & 63;

    float m2v[16];
#pragma unroll
    for (int a1 = 0; a1 < 16; ++a1)
        m2v[a1] = g_M2[(((a1 * 8 + j1) * 64 + j23) * 8 + i1) * 64 + i23];

#pragma unroll
    for (int j0 = 0; j0 < 8; ++j0) {
#pragma unroll
        for (int i0 = 0; i0 < 8; ++i0) {
            float s = 0.f;
#pragma unroll
            for (int a1 = 0; a1 < 16; ++a1)
                s += s_c0[j0 * 128 + i0 * 16 + a1] * m2v[a1];
            size_t row = (size_t)(j0 * 512 + j123);
            size_t col = (size_t)(i0 * 512 + i123);
            __nv_bfloat16 hi = __float2bfloat16(s);
            __nv_bfloat16 lo = __float2bfloat16(s - __bfloat162float(hi));
            __nv_bfloat16* b = g_Bp + row * 12288 + col;
            b[0] = hi;
            b[4096] = lo;
            b[8192] = hi;
        }
    }
}

// Convert x -> A' = [xhi | xhi | xlo]; 4 elements per thread.
__global__ void convert_x(const float* __restrict__ x) {
    int t = blockIdx.x * blockDim.x + threadIdx.x;  // 2,097,152
    int m = t >> 10;
    int k4 = (t & 1023) * 4;
    float4 v = *(const float4*)(x + (size_t)m * 4096 + k4);
    __nv_bfloat16 h0 = __float2bfloat16(v.x), h1 = __float2bfloat16(v.y);
    __nv_bfloat16 h2 = __float2bfloat16(v.z), h3 = __float2bfloat16(v.w);
    __nv_bfloat16 l0 = __float2bfloat16(v.x - __bfloat162float(h0));
    __nv_bfloat16 l1 = __float2bfloat16(v.y - __bfloat162float(h1));
    __nv_bfloat16 l2 = __float2bfloat16(v.z - __bfloat162float(h2));
    __nv_bfloat16 l3 = __float2bfloat16(v.w - __bfloat162float(h3));
    ushort4 hv = make_ushort4(__bfloat16_as_ushort(h0), __bfloat16_as_ushort(h1),
                              __bfloat16_as_ushort(h2), __bfloat16_as_ushort(h3));
    ushort4 lv = make_ushort4(__bfloat16_as_ushort(l0), __bfloat16_as_ushort(l1),
                              __bfloat16_as_ushort(l2), __bfloat16_as_ushort(l3));
    __nv_bfloat16* a = g_Ap + (size_t)m * 12288 + k4;
    *(ushort4*)(a) = hv;
    *(ushort4*)(a + 4096) = hv;
    *(ushort4*)(a + 8192) = lv;
}

// ---------------------------------------------------------------------------
// HMMA GEMM: C[2048,4096] = A'[2048,12288] @ B'[4096,12288]^T + bias
// 128x128 CTA tile, K-chunk 64 (128B SW128 rows), 3-stage cp.async pipeline,
// 8 warps, warp tile 32x64, mma.sync m16n8k16 bf16.
// ---------------------------------------------------------------------------
#define NKT 192                   // 12288 / 64
#define STAGE_BYTES 32768         // A 16KB + B 16KB
#define SM_TOTAL (3 * STAGE_BYTES)

__device__ __forceinline__ uint32_t smem_u32(const void* p) {
    uint32_t a;
    asm("{ .reg .u64 t; cvta.to.shared.u64 t, %1; cvt.u32.u64 %0, t; }"
        : "=r"(a) : "l"(p));
    return a;
}
__device__ __forceinline__ void cp16(uint32_t dst, const void* src) {
    asm volatile("cp.async.cg.shared.global [%0], [%1], 16;"
                 :: "r"(dst), "l"(src));
}
__device__ __forceinline__ void ldsm4(uint32_t (&r)[4], uint32_t addr) {
    asm volatile("ldmatrix.sync.aligned.m8n8.x4.shared.b16 {%0,%1,%2,%3}, [%4];"
                 : "=r"(r[0]), "=r"(r[1]), "=r"(r[2]), "=r"(r[3]) : "r"(addr));
}
__device__ __forceinline__ void mma16816(float (&d)[4], const uint32_t (&a)[4],
                                         uint32_t b0, uint32_t b1) {
    asm volatile(
        "mma.sync.aligned.m16n8k16.row.col.f32.bf16.bf16.f32 "
        "{%0,%1,%2,%3}, {%4,%5,%6,%7}, {%8,%9}, {%0,%1,%2,%3};"
        : "+f"(d[0]), "+f"(d[1]), "+f"(d[2]), "+f"(d[3])
        : "r"(a[0]), "r"(a[1]), "r"(a[2]), "r"(a[3]), "r"(b0), "r"(b1));
}

__global__ __launch_bounds__(256, 2)
void tt_gemm_mma(const float* __restrict__ bias, float* __restrict__ C) {
    extern __shared__ char smem[];
    const uint32_t sbase = smem_u32(smem);
    const int tid = threadIdx.x;
    const int wid = tid >> 5;
    const int lane = tid & 31;
    const int bm = blockIdx.y * 128;
    const int bn = blockIdx.x * 128;

    const int mw = wid >> 1;     // 0..3 -> m offset 32*mw
    const int nw = wid & 1;      // 0..1 -> n offset 64*nw

    // ---- cp.async producer indexing: 128 rows x 8 chunks(16B) per operand ----
    const int ld_row = tid >> 1;           // 0..127
    const int ld_seg = (tid & 1) * 4;      // chunk 0..3 or 4..7
    const int ld_xor = ld_row & 7;
    const __nv_bfloat16* agp = g_Ap + (size_t)(bm + ld_row) * 12288 + ld_seg * 8;
    const __nv_bfloat16* bgp = g_Bp + (size_t)(bn + ld_row) * 12288 + ld_seg * 8;
    const uint32_t a_dst_row = sbase + (uint32_t)ld_row * 128;
    const uint32_t b_dst_row = sbase + 16384u + (uint32_t)ld_row * 128;

    auto issue_stage = [&](int kt, int stg) {
        const uint32_t so = (uint32_t)stg * STAGE_BYTES;
        const __nv_bfloat16* asrc = agp + kt * 64;
        const __nv_bfloat16* bsrc = bgp + kt * 64;
#pragma unroll
        for (int q = 0; q < 4; ++q) {
            uint32_t sw = (uint32_t)(((ld_seg + q) ^ ld_xor) * 16);
            cp16(a_dst_row + so + sw, asrc + q * 8);
            cp16(b_dst_row + so + sw, bsrc + q * 8);
        }
        asm volatile("cp.async.commit_group;" ::: "memory");
    };

    // ---- ldmatrix consumer addresses ----
    // A: x4 -> mats {m0-7,k0},{m8-15,k0},{m0-7,k8},{m8-15,k8}
    const int a_r = mw * 32 + (lane & 15);           // + mi*16
    const int a_half = lane >> 4;                    // k half (16B)
    // B: x4 -> mats {n0-7,k0},{n0-7,k8},{n8-15,k0},{n8-15,k8}
    const int b_r = nw * 64 + (lane & 7) + ((lane >> 4) & 1) * 8;   // + g*16
    const int b_half = (lane >> 3) & 1;
    const int c_xor = lane & 7;   // row&7 == lane&7 for both roles

    float acc[2][8][4];
#pragma unroll
    for (int mi = 0; mi < 2; ++mi)
#pragma unroll
        for (int nf = 0; nf < 8; ++nf)
#pragma unroll
            for (int v = 0; v < 4; ++v) acc[mi][nf][v] = 0.f;

    // ---- prologue: stages 0,1 ----
    issue_stage(0, 0);
    issue_stage(1, 1);

    for (int kt = 0; kt < NKT; ++kt) {
        asm volatile("cp.async.wait_group 1;" ::: "memory");
        __syncthreads();
        if (kt + 2 < NKT) issue_stage(kt + 2, (kt + 2) % 3);

        const uint32_t so = (uint32_t)(kt % 3) * STAGE_BYTES;
        const uint32_t abase = sbase + so;
        const uint32_t bbase = sbase + so + 16384u;

#pragma unroll
        for (int s = 0; s < 4; ++s) {
            uint32_t a[2][4];
#pragma unroll
            for (int mi = 0; mi < 2; ++mi) {
                uint32_t ch = (uint32_t)((s * 2 + a_half) ^ c_xor);
                ldsm4(a[mi], abase + (uint32_t)(a_r + mi * 16) * 128 + ch * 16);
            }
            uint32_t b[4][4];
#pragma unroll
            for (int g = 0; g < 4; ++g) {
                uint32_t ch = (uint32_t)((s * 2 + b_half) ^ c_xor);
                ldsm4(b[g], bbase + (uint32_t)(b_r + g * 16) * 128 + ch * 16);
            }
#pragma unroll
            for (int mi = 0; mi < 2; ++mi)
#pragma unroll
                for (int g = 0; g < 4; ++g) {
                    mma16816(acc[mi][2 * g],     a[mi], b[g][0], b[g][1]);
                    mma16816(acc[mi][2 * g + 1], a[mi], b[g][2], b[g][3]);
                }
        }
    }

    // ---- epilogue: + bias, float2 stores ----
    const int er = lane >> 2;            // 0..7
    const int ec = (lane & 3) * 2;       // 0,2,4,6
#pragma unroll
    for (int mi = 0; mi < 2; ++mi) {
        const int m0 = bm + mw * 32 + mi * 16 + er;
#pragma unroll
        for (int nf = 0; nf < 8; ++nf) {
            const int n0 = bn + nw * 64 + nf * 8 + ec;
            const float2 bv = __ldg((const float2*)(bias + n0));
            float2 o0, o1;
            o0.x = acc[mi][nf][0] + bv.x;
            o0.y = acc[mi][nf][1] + bv.y;
            o1.x = acc[mi][nf][2] + bv.x;
            o1.y = acc[mi][nf][3] + bv.y;
            *(float2*)(C + (size_t)m0 * 4096 + n0) = o0;
            *(float2*)(C + (size_t)(m0 + 8) * 4096 + n0) = o1;
        }
    }
}

// ---------------------------------------------------------------------------
extern "C" void kernel_launch(void* const* d_in, const int* in_sizes, int n_in,
                              void* d_out, int out_size) {
    const float* x = (const float*)d_in[0];
    const float* core0 = (const float*)d_in[1];
    const float* core1 = (const float*)d_in[2];
    const float* core2 = (const float*)d_in[3];
    const float* core3 = (const float*)d_in[4];
    const float* bias = (const float*)d_in[5];
    float* out = (float*)d_out;

    cudaFuncSetAttribute(tt_gemm_mma, cudaFuncAttributeMaxDynamicSharedMemorySize, SM_TOTAL);

    convert_x<<<8192, 256>>>(x);
    compose_m1<<<256, 256>>>(core2, core3);
    compose_m2<<<16384, 256>>>(core1);
    compose_w<<<1024, 256>>>(core0);
    dim3 grid(4096 / 128, 2048 / 128);   // 32 x 16 = 512 CTAs
    tt_gemm_mma<<<grid, 256, SM_TOTAL>>>(bias, out);
}